// round 5
// baseline (speedup 1.0000x reference)
#include <cuda_runtime.h>
#include <cstdint>

// y[8192,4096] = x[8192,4096] @ W[4096,4096]^T + bias  (fp32)
// R3: TF32 mma.sync + 16x16 block-skip, 512 threads (16 warps) per CTA.
// CTA tile 128x256, warp tile 64x32 -> 64 acc regs, fits <=128 regs/thread
// so the SM carries 16 warps (vs 8 in R2) and hides LDS/mma latency.

#define MDIM 8192
#define NDIM 4096
#define KDIM 4096

#define BM 128
#define BN 256
#define BK 32
#define PAD_LD 36                       // 144B rows: 16B-aligned, conflict-free
#define A_STAGE (BM * PAD_LD)           // 4608 floats
#define B_STAGE (BN * PAD_LD)           // 9216 floats
#define SM_BIAS_OFF (2 * A_STAGE + 2 * B_STAGE)        // floats
#define SM_MASK_OFF (SM_BIAS_OFF + BN)
#define SMEM_FLOATS (SM_MASK_OFF + 128)
#define SMEM_BYTES (SMEM_FLOATS * 4)

#define NB_O (NDIM / 16)                // 256
#define NB_I (KDIM / 16)                // 256

__device__ float g_x[(size_t)MDIM * KDIM];
__device__ float g_w[(size_t)NDIM * KDIM];
__device__ uint32_t g_mask[NB_O * 8];   // [ob][8 words of 32 ib-bits]

// ---------------------------------------------------------------------------
__device__ __forceinline__ float rna_tf32(float x) {
    uint32_t r;
    asm("cvt.rna.tf32.f32 %0, %1;" : "=r"(r) : "f"(x));
    return __uint_as_float(r);
}

__global__ void cvt_tf32_kernel(const float4* __restrict__ in,
                                float4* __restrict__ out, int n4) {
    int i = blockIdx.x * blockDim.x + threadIdx.x;
    if (i >= n4) return;
    float4 v = in[i];
    v.x = rna_tf32(v.x); v.y = rna_tf32(v.y);
    v.z = rna_tf32(v.z); v.w = rna_tf32(v.w);
    out[i] = v;
}

__global__ void mask_kernel(const float* __restrict__ w) {
    int ob = blockIdx.x;
    int ib = threadIdx.x;
    const float* base = w + (size_t)(ob * 16) * KDIM + ib * 16;
    bool nz = false;
#pragma unroll
    for (int r = 0; r < 16; r++) {
        const float4* p = reinterpret_cast<const float4*>(base + (size_t)r * KDIM);
#pragma unroll
        for (int c = 0; c < 4; c++) {
            float4 v = p[c];
            nz |= (v.x != 0.0f) | (v.y != 0.0f) | (v.z != 0.0f) | (v.w != 0.0f);
        }
    }
    uint32_t bal = __ballot_sync(0xffffffffu, nz);
    if ((ib & 31) == 0) g_mask[ob * 8 + (ib >> 5)] = bal;
}

// ---------------------------------------------------------------------------
__device__ __forceinline__ void cp_async16(uint32_t sa, const void* gptr) {
    asm volatile("cp.async.cg.shared.global [%0], [%1], 16;\n" ::"r"(sa), "l"(gptr));
}
#define CP_COMMIT() asm volatile("cp.async.commit_group;\n" ::: "memory")
#define CP_WAIT0()  asm volatile("cp.async.wait_group 0;\n" ::: "memory")

// 512 threads: A 1024 chunks -> 2/thread, B 2048 chunks -> 4/thread
__device__ __forceinline__ void load_stage(uint32_t sA_u, uint32_t sB_u,
                                           const float* gA, const float* gB,
                                           int kt, int tid,
                                           const uint32_t* sMask) {
    const int koff = kt * BK;
    const int c = tid & 7;
    const int r0 = tid >> 3;                         // 0..63
#pragma unroll
    for (int j = 0; j < 2; j++) {
        int row = r0 + j * 64;
        cp_async16(sA_u + (row * PAD_LD + c * 4) * 4,
                   gA + (size_t)row * KDIM + koff + c * 4);
    }
    const int ib = 2 * kt + (c >> 2);
    const int wsel = ib >> 5;
    const int bsel = ib & 31;
#pragma unroll
    for (int j = 0; j < 4; j++) {
        int row = r0 + j * 64;
        int obl = row >> 4;
        uint32_t mword = sMask[obl * 8 + wsel];
        if ((mword >> bsel) & 1u) {
            cp_async16(sB_u + (row * PAD_LD + c * 4) * 4,
                       gB + (size_t)row * KDIM + koff + c * 4);
        }
    }
}

// ---------------------------------------------------------------------------
// GEMM: CTA 128x256, 16 warps as 2(M) x 8(N), warp tile 64x32 (mt=4, nt=4)
// ---------------------------------------------------------------------------
__global__ __launch_bounds__(512, 1)
void gemm_tf32_sparse(const float* __restrict__ bias, float* __restrict__ out) {
    extern __shared__ float smem[];
    float* sA = smem;
    float* sB = smem + 2 * A_STAGE;
    float* sBias = smem + SM_BIAS_OFF;
    uint32_t* sMask = reinterpret_cast<uint32_t*>(smem + SM_MASK_OFF);
    const uint32_t sA_u = (uint32_t)__cvta_generic_to_shared(sA);
    const uint32_t sB_u = (uint32_t)__cvta_generic_to_shared(sB);

    const int tid  = threadIdx.x;
    const int lane = tid & 31;
    const int warp = tid >> 5;
    const int wm = warp >> 3;        // 0..1
    const int wn = warp & 7;         // 0..7
    const int g = lane >> 2;
    const int t = lane & 3;

    const int bn = blockIdx.x * BN;
    const int bm = blockIdx.y * BM;

    if (tid < BN) sBias[tid] = bias[bn + tid];
    if (tid < 128) sMask[tid] = g_mask[(bn >> 1) + tid];
    __syncthreads();

    const float* gA = g_x + (size_t)bm * KDIM;
    const float* gB = g_w + (size_t)bn * KDIM;

    float acc[4][4][4];
#pragma unroll
    for (int i = 0; i < 4; i++)
#pragma unroll
        for (int j = 0; j < 4; j++)
#pragma unroll
            for (int r = 0; r < 4; r++) acc[i][j][r] = 0.0f;

    load_stage(sA_u, sB_u, gA, gB, 0, tid, sMask);
    CP_COMMIT();

    uint32_t mw[2];                  // this warp's 2 o-blocks
    const int NKT = KDIM / BK;       // 128

    for (int kt = 0; kt < NKT; kt++) {
        const int cur = kt & 1;
        CP_WAIT0();
        __syncthreads();
        if (kt + 1 < NKT) {
            const int nxt = cur ^ 1;
            load_stage(sA_u + nxt * A_STAGE * 4, sB_u + nxt * B_STAGE * 4,
                       gA, gB, kt + 1, tid, sMask);
        }
        CP_COMMIT();

        if ((kt & 15) == 0) {
#pragma unroll
            for (int q = 0; q < 2; q++)
                mw[q] = sMask[(wn * 2 + q) * 8 + (kt >> 4)];
        }
        const int bbase = (kt & 15) * 2;

        const float* As_ = sA + cur * A_STAGE;
        const float* Bs_ = sB + cur * B_STAGE;

#pragma unroll
        for (int kk = 0; kk < 4; kk++) {
            const int k0 = kk * 8;
            uint32_t a[4][4];
#pragma unroll
            for (int mt = 0; mt < 4; mt++) {
                int r = wm * 64 + mt * 16 + g;
                a[mt][0] = __float_as_uint(As_[r * PAD_LD + k0 + t]);
                a[mt][1] = __float_as_uint(As_[(r + 8) * PAD_LD + k0 + t]);
                a[mt][2] = __float_as_uint(As_[r * PAD_LD + k0 + t + 4]);
                a[mt][3] = __float_as_uint(As_[(r + 8) * PAD_LD + k0 + t + 4]);
            }
#pragma unroll
            for (int q = 0; q < 2; q++) {
                if ((mw[q] >> (bbase + (kk >> 1))) & 1u) {
#pragma unroll
                    for (int nt2 = 0; nt2 < 2; nt2++) {
                        const int nt = q * 2 + nt2;
                        const int ccol = wn * 32 + nt * 8 + g;
                        uint32_t b0 = __float_as_uint(Bs_[ccol * PAD_LD + k0 + t]);
                        uint32_t b1 = __float_as_uint(Bs_[ccol * PAD_LD + k0 + t + 4]);
#pragma unroll
                        for (int mt = 0; mt < 4; mt++) {
                            asm volatile(
                                "mma.sync.aligned.m16n8k8.row.col.f32.tf32.tf32.f32 "
                                "{%0,%1,%2,%3}, {%4,%5,%6,%7}, {%8,%9}, {%0,%1,%2,%3};\n"
                                : "+f"(acc[mt][nt][0]), "+f"(acc[mt][nt][1]),
                                  "+f"(acc[mt][nt][2]), "+f"(acc[mt][nt][3])
                                : "r"(a[mt][0]), "r"(a[mt][1]),
                                  "r"(a[mt][2]), "r"(a[mt][3]),
                                  "r"(b0), "r"(b1));
                        }
                    }
                }
            }
        }
        __syncthreads();
    }

    // epilogue
#pragma unroll
    for (int mt = 0; mt < 4; mt++) {
        int r0 = bm + wm * 64 + mt * 16 + g;
#pragma unroll
        for (int nt = 0; nt < 4; nt++) {
            int cl = wn * 32 + nt * 8 + 2 * t;
            int c = bn + cl;
            float b0 = sBias[cl], b1 = sBias[cl + 1];
            float2 v0 = make_float2(acc[mt][nt][0] + b0, acc[mt][nt][1] + b1);
            float2 v1 = make_float2(acc[mt][nt][2] + b0, acc[mt][nt][3] + b1);
            *reinterpret_cast<float2*>(out + (size_t)r0 * NDIM + c) = v0;
            *reinterpret_cast<float2*>(out + (size_t)(r0 + 8) * NDIM + c) = v1;
        }
    }
}

// ---------------------------------------------------------------------------
extern "C" void kernel_launch(void* const* d_in, const int* in_sizes, int n_in,
                              void* d_out, int out_size) {
    const float* x    = (const float*)d_in[0];
    const float* w    = (const float*)d_in[1];
    const float* bias = (const float*)d_in[2];
    float* y = (float*)d_out;

    void* gx_ptr = nullptr;
    void* gw_ptr = nullptr;
    cudaGetSymbolAddress(&gx_ptr, g_x);
    cudaGetSymbolAddress(&gw_ptr, g_w);

    mask_kernel<<<NB_O, 256>>>(w);

    const int n4x = MDIM * KDIM / 4;
    const int n4w = NDIM * KDIM / 4;
    cvt_tf32_kernel<<<(n4x + 255) / 256, 256>>>((const float4*)x, (float4*)gx_ptr, n4x);
    cvt_tf32_kernel<<<(n4w + 255) / 256, 256>>>((const float4*)w, (float4*)gw_ptr, n4w);

    cudaFuncSetAttribute(gemm_tf32_sparse,
                         cudaFuncAttributeMaxDynamicSharedMemorySize, SMEM_BYTES);
    dim3 grid(NDIM / BN, MDIM / BM);   // 16 x 64
    gemm_tf32_sparse<<<grid, 512, SMEM_BYTES>>>(bias, y);
}

// round 6
// speedup vs baseline: 1.5413x; 1.5413x over previous
#include <cuda_runtime.h>
#include <cstdint>

// y[8192,4096] = x[8192,4096] @ W[4096,4096]^T + bias  (fp32)
// R5: back to R2 shape (CTA 128x256, 8 warps, warp tile 64x64, block-skip),
// fragment loads via ldmatrix.x4 (tf32 fragments == m8n8.b16 x4 viewed as
// 8x4 b32). 8 LDSM per kk instead of 32 scalar LDS + address math.

#define MDIM 8192
#define NDIM 4096
#define KDIM 4096

#define BM 128
#define BN 256
#define BK 32
#define PAD_LD 36                       // 144B rows; LDSM phase hits all 32 banks
#define A_STAGE (BM * PAD_LD)
#define B_STAGE (BN * PAD_LD)
#define SM_BIAS_OFF (2 * A_STAGE + 2 * B_STAGE)
#define SM_MASK_OFF (SM_BIAS_OFF + BN)
#define SMEM_FLOATS (SM_MASK_OFF + 128)
#define SMEM_BYTES (SMEM_FLOATS * 4)

#define NB_O (NDIM / 16)
#define NB_I (KDIM / 16)

__device__ float g_x[(size_t)MDIM * KDIM];
__device__ float g_w[(size_t)NDIM * KDIM];
__device__ uint32_t g_mask[NB_O * 8];

// ---------------------------------------------------------------------------
__device__ __forceinline__ float rna_tf32(float x) {
    uint32_t r;
    asm("cvt.rna.tf32.f32 %0, %1;" : "=r"(r) : "f"(x));
    return __uint_as_float(r);
}

__global__ void cvt_tf32_kernel(const float4* __restrict__ in,
                                float4* __restrict__ out, int n4) {
    int i = blockIdx.x * blockDim.x + threadIdx.x;
    if (i >= n4) return;
    float4 v = in[i];
    v.x = rna_tf32(v.x); v.y = rna_tf32(v.y);
    v.z = rna_tf32(v.z); v.w = rna_tf32(v.w);
    out[i] = v;
}

__global__ void mask_kernel(const float* __restrict__ w) {
    int ob = blockIdx.x;
    int ib = threadIdx.x;
    const float* base = w + (size_t)(ob * 16) * KDIM + ib * 16;
    bool nz = false;
#pragma unroll
    for (int r = 0; r < 16; r++) {
        const float4* p = reinterpret_cast<const float4*>(base + (size_t)r * KDIM);
#pragma unroll
        for (int c = 0; c < 4; c++) {
            float4 v = p[c];
            nz |= (v.x != 0.0f) | (v.y != 0.0f) | (v.z != 0.0f) | (v.w != 0.0f);
        }
    }
    uint32_t bal = __ballot_sync(0xffffffffu, nz);
    if ((ib & 31) == 0) g_mask[ob * 8 + (ib >> 5)] = bal;
}

// ---------------------------------------------------------------------------
__device__ __forceinline__ void cp_async16(uint32_t sa, const void* gptr) {
    asm volatile("cp.async.cg.shared.global [%0], [%1], 16;\n" ::"r"(sa), "l"(gptr));
}
#define CP_COMMIT() asm volatile("cp.async.commit_group;\n" ::: "memory")
#define CP_WAIT0()  asm volatile("cp.async.wait_group 0;\n" ::: "memory")

__device__ __forceinline__ void ldsm4(uint32_t& r0, uint32_t& r1,
                                      uint32_t& r2, uint32_t& r3, uint32_t addr) {
    asm volatile("ldmatrix.sync.aligned.m8n8.x4.shared.b16 {%0,%1,%2,%3}, [%4];"
                 : "=r"(r0), "=r"(r1), "=r"(r2), "=r"(r3) : "r"(addr));
}

// A: 128 rows x 32 floats (4 chunks/thread), B: 256 rows, zero-block chunks skipped
__device__ __forceinline__ void load_stage(uint32_t sA_u, uint32_t sB_u,
                                           const float* gA, const float* gB,
                                           int kt, int tid,
                                           const uint32_t* sMask) {
    const int koff = kt * BK;
    const int c = tid & 7;
    const int r0 = tid >> 3;
#pragma unroll
    for (int j = 0; j < 4; j++) {
        int row = r0 + j * 32;
        cp_async16(sA_u + (row * PAD_LD + c * 4) * 4,
                   gA + (size_t)row * KDIM + koff + c * 4);
    }
    const int ib = 2 * kt + (c >> 2);
    const int wsel = ib >> 5;
    const int bsel = ib & 31;
#pragma unroll
    for (int j = 0; j < 8; j++) {
        int row = r0 + j * 32;
        int obl = row >> 4;
        uint32_t mword = sMask[obl * 8 + wsel];
        if ((mword >> bsel) & 1u) {
            cp_async16(sB_u + (row * PAD_LD + c * 4) * 4,
                       gB + (size_t)row * KDIM + koff + c * 4);
        }
    }
}

// ---------------------------------------------------------------------------
// GEMM: CTA 128x256, 8 warps 2(M) x 4(N), warp tile 64x64 (mt=4, nt=8), LDSM
// ---------------------------------------------------------------------------
__global__ __launch_bounds__(256, 1)
void gemm_tf32_sparse(const float* __restrict__ bias, float* __restrict__ out) {
    extern __shared__ float smem[];
    float* sA = smem;
    float* sB = smem + 2 * A_STAGE;
    float* sBias = smem + SM_BIAS_OFF;
    uint32_t* sMask = reinterpret_cast<uint32_t*>(smem + SM_MASK_OFF);
    const uint32_t sA_u = (uint32_t)__cvta_generic_to_shared(sA);
    const uint32_t sB_u = (uint32_t)__cvta_generic_to_shared(sB);

    const int tid  = threadIdx.x;
    const int lane = tid & 31;
    const int warp = tid >> 5;
    const int wm = warp >> 2;        // 0..1
    const int wn = warp & 3;         // 0..3
    const int g = lane >> 2;
    const int t = lane & 3;

    const int bn = blockIdx.x * BN;
    const int bm = blockIdx.y * BM;

    sBias[tid] = bias[bn + tid];
    if (tid < 128) sMask[tid] = g_mask[(bn >> 1) + tid];
    __syncthreads();

    const float* gA = g_x + (size_t)bm * KDIM;
    const float* gB = g_w + (size_t)bn * KDIM;

    // per-lane LDSM row offset (same formula for A rows and B cols):
    // matrices 0/1: rows base+(l&7), base+8+(l&7); matrices 2/3: +4 floats in k
    const int lmoff = (((lane & 7) + ((lane >> 3) & 1) * 8) * PAD_LD
                       + (lane >> 4) * 4) * 4;      // bytes

    float acc[4][8][4];
#pragma unroll
    for (int i = 0; i < 4; i++)
#pragma unroll
        for (int j = 0; j < 8; j++)
#pragma unroll
            for (int r = 0; r < 4; r++) acc[i][j][r] = 0.0f;

    load_stage(sA_u, sB_u, gA, gB, 0, tid, sMask);
    CP_COMMIT();

    uint32_t mw[4];
    const int NKT = KDIM / BK;       // 128

    for (int kt = 0; kt < NKT; kt++) {
        const int cur = kt & 1;
        CP_WAIT0();
        __syncthreads();
        if (kt + 1 < NKT) {
            const int nxt = cur ^ 1;
            load_stage(sA_u + nxt * A_STAGE * 4, sB_u + nxt * B_STAGE * 4,
                       gA, gB, kt + 1, tid, sMask);
        }
        CP_COMMIT();

        if ((kt & 15) == 0) {
#pragma unroll
            for (int q = 0; q < 4; q++)
                mw[q] = sMask[(wn * 4 + q) * 8 + (kt >> 4)];
        }
        const int bbase = (kt & 15) * 2;

        const uint32_t As_u = sA_u + cur * A_STAGE * 4;
        const uint32_t Bs_u = sB_u + cur * B_STAGE * 4;
        const uint32_t aBase = As_u + (uint32_t)(wm * 64 * PAD_LD * 4) + lmoff;
        const uint32_t bBase = Bs_u + (uint32_t)(wn * 64 * PAD_LD * 4) + lmoff;

#pragma unroll
        for (int kk = 0; kk < 4; kk++) {
            const uint32_t kOff = (uint32_t)(kk * 8 * 4);
            uint32_t a[4][4];
#pragma unroll
            for (int mt = 0; mt < 4; mt++) {
                ldsm4(a[mt][0], a[mt][1], a[mt][2], a[mt][3],
                      aBase + (uint32_t)(mt * 16 * PAD_LD * 4) + kOff);
            }
#pragma unroll
            for (int q = 0; q < 4; q++) {
                if ((mw[q] >> (bbase + (kk >> 1))) & 1u) {
                    uint32_t b00, b10, b01, b11;   // [nt2][kfrag]
                    ldsm4(b00, b10, b01, b11,
                          bBase + (uint32_t)(q * 16 * PAD_LD * 4) + kOff);
#pragma unroll
                    for (int nt2 = 0; nt2 < 2; nt2++) {
                        const int nt = q * 2 + nt2;
                        const uint32_t bb0 = nt2 ? b10 : b00;
                        const uint32_t bb1 = nt2 ? b11 : b01;
#pragma unroll
                        for (int mt = 0; mt < 4; mt++) {
                            asm volatile(
                                "mma.sync.aligned.m16n8k8.row.col.f32.tf32.tf32.f32 "
                                "{%0,%1,%2,%3}, {%4,%5,%6,%7}, {%8,%9}, {%0,%1,%2,%3};\n"
                                : "+f"(acc[mt][nt][0]), "+f"(acc[mt][nt][1]),
                                  "+f"(acc[mt][nt][2]), "+f"(acc[mt][nt][3])
                                : "r"(a[mt][0]), "r"(a[mt][1]),
                                  "r"(a[mt][2]), "r"(a[mt][3]),
                                  "r"(bb0), "r"(bb1));
                        }
                    }
                }
            }
        }
        __syncthreads();
    }

    // epilogue: bias add + fp32 store
#pragma unroll
    for (int mt = 0; mt < 4; mt++) {
        int r0 = bm + wm * 64 + mt * 16 + g;
#pragma unroll
        for (int nt = 0; nt < 8; nt++) {
            int cl = wn * 64 + nt * 8 + 2 * t;
            int c = bn + cl;
            float b0 = sBias[cl], b1 = sBias[cl + 1];
            float2 v0 = make_float2(acc[mt][nt][0] + b0, acc[mt][nt][1] + b1);
            float2 v1 = make_float2(acc[mt][nt][2] + b0, acc[mt][nt][3] + b1);
            *reinterpret_cast<float2*>(out + (size_t)r0 * NDIM + c) = v0;
            *reinterpret_cast<float2*>(out + (size_t)(r0 + 8) * NDIM + c) = v1;
        }
    }
}

// ---------------------------------------------------------------------------
extern "C" void kernel_launch(void* const* d_in, const int* in_sizes, int n_in,
                              void* d_out, int out_size) {
    const float* x    = (const float*)d_in[0];
    const float* w    = (const float*)d_in[1];
    const float* bias = (const float*)d_in[2];
    float* y = (float*)d_out;

    void* gx_ptr = nullptr;
    void* gw_ptr = nullptr;
    cudaGetSymbolAddress(&gx_ptr, g_x);
    cudaGetSymbolAddress(&gw_ptr, g_w);

    mask_kernel<<<NB_O, 256>>>(w);

    const int n4x = MDIM * KDIM / 4;
    const int n4w = NDIM * KDIM / 4;
    cvt_tf32_kernel<<<(n4x + 255) / 256, 256>>>((const float4*)x, (float4*)gx_ptr, n4x);
    cvt_tf32_kernel<<<(n4w + 255) / 256, 256>>>((const float4*)w, (float4*)gw_ptr, n4w);

    cudaFuncSetAttribute(gemm_tf32_sparse,
                         cudaFuncAttributeMaxDynamicSharedMemorySize, SMEM_BYTES);
    dim3 grid(NDIM / BN, MDIM / BM);   // 16 x 64
    gemm_tf32_sparse<<<grid, 256, SMEM_BYTES>>>(bias, y);
}

// round 8
// speedup vs baseline: 1.6077x; 1.0431x over previous
#include <cuda_runtime.h>
#include <cstdint>

// y[8192,4096] = x[8192,4096] @ W[4096,4096]^T + bias  (fp32)
// R6: TF32 mma.sync + 16x16 block-skip + LDSM fragments, CTA 128x128
// (8 warps, warp tile 64x32), 2 CTAs/SM so barrier stalls in one CTA
// overlap with compute in the other.

#define MDIM 8192
#define NDIM 4096
#define KDIM 4096

#define BM 128
#define BN 128
#define BK 32
#define PAD_LD 36
#define A_STAGE (BM * PAD_LD)           // 4608 floats
#define B_STAGE (BN * PAD_LD)           // 4608 floats
#define SM_BIAS_OFF (2 * A_STAGE + 2 * B_STAGE)
#define SM_MASK_OFF (SM_BIAS_OFF + BN)
#define SMEM_FLOATS (SM_MASK_OFF + 64)
#define SMEM_BYTES (SMEM_FLOATS * 4)    // ~74.5 KB -> 2 CTAs/SM

#define NB_O (NDIM / 16)
#define NB_I (KDIM / 16)

__device__ float g_x[(size_t)MDIM * KDIM];
__device__ float g_w[(size_t)NDIM * KDIM];
__device__ uint32_t g_mask[NB_O * 8];

// ---------------------------------------------------------------------------
__device__ __forceinline__ float rna_tf32(float x) {
    uint32_t r;
    asm("cvt.rna.tf32.f32 %0, %1;" : "=r"(r) : "f"(x));
    return __uint_as_float(r);
}

__global__ void cvt_tf32_kernel(const float4* __restrict__ in,
                                float4* __restrict__ out, int n4) {
    int i = blockIdx.x * blockDim.x + threadIdx.x;
    if (i >= n4) return;
    float4 v = in[i];
    v.x = rna_tf32(v.x); v.y = rna_tf32(v.y);
    v.z = rna_tf32(v.z); v.w = rna_tf32(v.w);
    out[i] = v;
}

__global__ void mask_kernel(const float* __restrict__ w) {
    int ob = blockIdx.x;
    int ib = threadIdx.x;
    const float* base = w + (size_t)(ob * 16) * KDIM + ib * 16;
    bool nz = false;
#pragma unroll
    for (int r = 0; r < 16; r++) {
        const float4* p = reinterpret_cast<const float4*>(base + (size_t)r * KDIM);
#pragma unroll
        for (int c = 0; c < 4; c++) {
            float4 v = p[c];
            nz |= (v.x != 0.0f) | (v.y != 0.0f) | (v.z != 0.0f) | (v.w != 0.0f);
        }
    }
    uint32_t bal = __ballot_sync(0xffffffffu, nz);
    if ((ib & 31) == 0) g_mask[ob * 8 + (ib >> 5)] = bal;
}

// ---------------------------------------------------------------------------
__device__ __forceinline__ void cp_async16(uint32_t sa, const void* gptr) {
    asm volatile("cp.async.cg.shared.global [%0], [%1], 16;\n" ::"r"(sa), "l"(gptr));
}
#define CP_COMMIT() asm volatile("cp.async.commit_group;\n" ::: "memory")
#define CP_WAIT0()  asm volatile("cp.async.wait_group 0;\n" ::: "memory")

__device__ __forceinline__ void ldsm4(uint32_t& r0, uint32_t& r1,
                                      uint32_t& r2, uint32_t& r3, uint32_t addr) {
    asm volatile("ldmatrix.sync.aligned.m8n8.x4.shared.b16 {%0,%1,%2,%3}, [%4];"
                 : "=r"(r0), "=r"(r1), "=r"(r2), "=r"(r3) : "r"(addr));
}

// 256 threads: A 1024 chunks -> 4/thread, B 1024 chunks -> 4/thread (masked)
__device__ __forceinline__ void load_stage(uint32_t sA_u, uint32_t sB_u,
                                           const float* gA, const float* gB,
                                           int kt, int tid,
                                           const uint32_t* sMask) {
    const int koff = kt * BK;
    const int c = tid & 7;
    const int r0 = tid >> 3;                 // 0..31
#pragma unroll
    for (int j = 0; j < 4; j++) {
        int row = r0 + j * 32;
        cp_async16(sA_u + (row * PAD_LD + c * 4) * 4,
                   gA + (size_t)row * KDIM + koff + c * 4);
    }
    const int ib = 2 * kt + (c >> 2);
    const int wsel = ib >> 5;
    const int bsel = ib & 31;
#pragma unroll
    for (int j = 0; j < 4; j++) {
        int row = r0 + j * 32;
        int obl = row >> 4;                  // 0..7
        uint32_t mword = sMask[obl * 8 + wsel];
        if ((mword >> bsel) & 1u) {
            cp_async16(sB_u + (row * PAD_LD + c * 4) * 4,
                       gB + (size_t)row * KDIM + koff + c * 4);
        }
    }
}

// ---------------------------------------------------------------------------
// GEMM: CTA 128x128, 8 warps 2(M) x 4(N), warp tile 64x32 (mt=4, nt=4), LDSM
// ---------------------------------------------------------------------------
__global__ __launch_bounds__(256, 2)
void gemm_tf32_sparse(const float* __restrict__ bias, float* __restrict__ out) {
    extern __shared__ float smem[];
    float* sA = smem;
    float* sB = smem + 2 * A_STAGE;
    float* sBias = smem + SM_BIAS_OFF;
    uint32_t* sMask = reinterpret_cast<uint32_t*>(smem + SM_MASK_OFF);
    const uint32_t sA_u = (uint32_t)__cvta_generic_to_shared(sA);
    const uint32_t sB_u = (uint32_t)__cvta_generic_to_shared(sB);

    const int tid  = threadIdx.x;
    const int lane = tid & 31;
    const int warp = tid >> 5;
    const int wm = warp >> 2;        // 0..1
    const int wn = warp & 3;         // 0..3
    const int g = lane >> 2;
    const int t = lane & 3;

    const int bn = blockIdx.x * BN;
    const int bm = blockIdx.y * BM;

    if (tid < BN) sBias[tid] = bias[bn + tid];
    if (tid < 64) sMask[tid] = g_mask[(bn >> 4) * 8 + tid];  // 8 ob rows x 8 words
    __syncthreads();

    const float* gA = g_x + (size_t)bm * KDIM;
    const float* gB = g_w + (size_t)bn * KDIM;

    // per-lane ldmatrix source offset (bytes), shared by A rows / B cols
    const int lmoff = (((lane & 7) + ((lane >> 3) & 1) * 8) * PAD_LD
                       + (lane >> 4) * 4) * 4;

    float acc[4][4][4];
#pragma unroll
    for (int i = 0; i < 4; i++)
#pragma unroll
        for (int j = 0; j < 4; j++)
#pragma unroll
            for (int r = 0; r < 4; r++) acc[i][j][r] = 0.0f;

    load_stage(sA_u, sB_u, gA, gB, 0, tid, sMask);
    CP_COMMIT();

    uint32_t mw[2];                  // this warp's 2 o-blocks
    const int NKT = KDIM / BK;       // 128

    for (int kt = 0; kt < NKT; kt++) {
        const int cur = kt & 1;
        CP_WAIT0();
        __syncthreads();
        if (kt + 1 < NKT) {
            const int nxt = cur ^ 1;
            load_stage(sA_u + nxt * A_STAGE * 4, sB_u + nxt * B_STAGE * 4,
                       gA, gB, kt + 1, tid, sMask);
        }
        CP_COMMIT();

        if ((kt & 15) == 0) {
#pragma unroll
            for (int q = 0; q < 2; q++)
                mw[q] = sMask[(wn * 2 + q) * 8 + (kt >> 4)];
        }
        const int bbase = (kt & 15) * 2;

        const uint32_t As_u = sA_u + cur * A_STAGE * 4;
        const uint32_t Bs_u = sB_u + cur * B_STAGE * 4;
        const uint32_t aBase = As_u + (uint32_t)(wm * 64 * PAD_LD * 4) + lmoff;
        const uint32_t bBase = Bs_u + (uint32_t)(wn * 32 * PAD_LD * 4) + lmoff;

#pragma unroll
        for (int kk = 0; kk < 4; kk++) {
            const uint32_t kOff = (uint32_t)(kk * 8 * 4);
            uint32_t a[4][4];
#pragma unroll
            for (int mt = 0; mt < 4; mt++) {
                ldsm4(a[mt][0], a[mt][1], a[mt][2], a[mt][3],
                      aBase + (uint32_t)(mt * 16 * PAD_LD * 4) + kOff);
            }
#pragma unroll
            for (int q = 0; q < 2; q++) {
                if ((mw[q] >> (bbase + (kk >> 1))) & 1u) {
                    uint32_t b00, b10, b01, b11;
                    ldsm4(b00, b10, b01, b11,
                          bBase + (uint32_t)(q * 16 * PAD_LD * 4) + kOff);
#pragma unroll
                    for (int nt2 = 0; nt2 < 2; nt2++) {
                        const int nt = q * 2 + nt2;
                        const uint32_t bb0 = nt2 ? b10 : b00;
                        const uint32_t bb1 = nt2 ? b11 : b01;
#pragma unroll
                        for (int mt = 0; mt < 4; mt++) {
                            asm volatile(
                                "mma.sync.aligned.m16n8k8.row.col.f32.tf32.tf32.f32 "
                                "{%0,%1,%2,%3}, {%4,%5,%6,%7}, {%8,%9}, {%0,%1,%2,%3};\n"
                                : "+f"(acc[mt][nt][0]), "+f"(acc[mt][nt][1]),
                                  "+f"(acc[mt][nt][2]), "+f"(acc[mt][nt][3])
                                : "r"(a[mt][0]), "r"(a[mt][1]),
                                  "r"(a[mt][2]), "r"(a[mt][3]),
                                  "r"(bb0), "r"(bb1));
                        }
                    }
                }
            }
        }
        __syncthreads();
    }

    // epilogue: bias add + fp32 store
#pragma unroll
    for (int mt = 0; mt < 4; mt++) {
        int r0 = bm + wm * 64 + mt * 16 + g;
#pragma unroll
        for (int nt = 0; nt < 4; nt++) {
            int cl = wn * 32 + nt * 8 + 2 * t;
            int c = bn + cl;
            float b0 = sBias[cl], b1 = sBias[cl + 1];
            float2 v0 = make_float2(acc[mt][nt][0] + b0, acc[mt][nt][1] + b1);
            float2 v1 = make_float2(acc[mt][nt][2] + b0, acc[mt][nt][3] + b1);
            *reinterpret_cast<float2*>(out + (size_t)r0 * NDIM + c) = v0;
            *reinterpret_cast<float2*>(out + (size_t)(r0 + 8) * NDIM + c) = v1;
        }
    }
}

// ---------------------------------------------------------------------------
extern "C" void kernel_launch(void* const* d_in, const int* in_sizes, int n_in,
                              void* d_out, int out_size) {
    const float* x    = (const float*)d_in[0];
    const float* w    = (const float*)d_in[1];
    const float* bias = (const float*)d_in[2];
    float* y = (float*)d_out;

    void* gx_ptr = nullptr;
    void* gw_ptr = nullptr;
    cudaGetSymbolAddress(&gx_ptr, g_x);
    cudaGetSymbolAddress(&gw_ptr, g_w);

    mask_kernel<<<NB_O, 256>>>(w);

    const int n4x = MDIM * KDIM / 4;
    const int n4w = NDIM * KDIM / 4;
    cvt_tf32_kernel<<<(n4x + 255) / 256, 256>>>((const float4*)x, (float4*)gx_ptr, n4x);
    cvt_tf32_kernel<<<(n4w + 255) / 256, 256>>>((const float4*)w, (float4*)gw_ptr, n4w);

    cudaFuncSetAttribute(gemm_tf32_sparse,
                         cudaFuncAttributeMaxDynamicSharedMemorySize, SMEM_BYTES);
    dim3 grid(NDIM / BN, MDIM / BM);   // 32 x 64
    gemm_tf32_sparse<<<grid, 256, SMEM_BYTES>>>(bias, y);
}